// round 16
// baseline (speedup 1.0000x reference)
#include <cuda_runtime.h>

// ---------------------------------------------------------------------------
// Earth4D multires hash encode, sm_103a
// s2: densify(quad-pack)  ||  s0: reduce(ecef+minmax+hist-zero) ->
// normalize(21-bit morton key + hist) -> scanA -> scatter(+chunk scan)
// ; join -> encode
// Dense cell = 32B quad [f(y,z), f(y,z+1), f(y+1,z), f(y+1,z+1)]:
// one point needs only 2 cells (x0,x1), each 2 same-line float4 loads.
// ---------------------------------------------------------------------------

#define TBL_SIZE  (1 << 19)
#define TBL_MASK  0x7FFFFu
#define MAXN      500000
#define DEG2RAD   0.017453292519943295f
#define EARTH_R   6371000.0f

#define SP_TOTAL   2111933        // dense cells, spatial levels 0..8
#define TM_TOTAL   77756          // dense cells per temporal encoding
#define DENSE_TOTAL (SP_TOTAL + 3 * TM_TOTAL)   // 2345201 cells (x2 float4 each)

#define NBINS      2097152        // 21-bit spatial morton (x7,y7,z7)
#define NCHUNK     2048
#define RED_BLOCKS 232
#define ZERO_BLOCKS 2048

// idempotent across graph replays: atomics re-derive the same min/max
__device__ float  g_red[8] = {3e38f, 3e38f, 3e38f, -3e38f, -3e38f, -3e38f, 3e38f, -3e38f};
__device__ float4 g_u[MAXN];
__device__ float4 g_su[MAXN];
__device__ int    g_sidx[MAXN];
__device__ int    g_key[MAXN];
__device__ int    g_hist[NBINS];
__device__ int    g_off[NBINS];
__device__ int    g_bsum[NCHUNK];
__device__ float4 g_dense[2 * DENSE_TOTAL];   // 2 float4 per cell (32B quad)

// per-(enc*16+lvl) descriptor: {dense cell offset(-1 = hashed), r01, r2, 0}
__constant__ int4 PAIR_DESC[64] = {
    {0,16,16,0},{4096,20,20,0},{12096,25,25,0},{27721,32,32,0},
    {60489,40,40,0},{124489,51,51,0},{257140,64,64,0},{519284,81,81,0},
    {1050725,102,102,0},{-1,128,128,0},{-1,161,161,0},{-1,203,203,0},
    {-1,256,256,0},{-1,323,323,0},{-1,406,406,0},{-1,512,512,0},
    {2111933,8,8,0},{2112445,9,8,0},{2113093,10,9,0},{2113993,11,9,0},
    {2115082,12,10,0},{2116522,13,10,0},{2118212,14,11,0},{2120368,15,11,0},
    {2122843,17,12,0},{2126311,18,12,0},{2130199,20,13,0},{2135399,22,13,0},
    {2141691,24,14,0},{2149755,27,15,0},{2160690,29,15,0},{2173305,32,16,0},
    {2189689,8,8,0},{2190201,9,8,0},{2190849,10,9,0},{2191749,11,9,0},
    {2192838,12,10,0},{2194278,13,10,0},{2195968,14,11,0},{2198124,15,11,0},
    {2200599,17,12,0},{2204067,18,12,0},{2207955,20,13,0},{2213155,22,13,0},
    {2219447,24,14,0},{2227511,27,15,0},{2238446,29,15,0},{2251061,32,16,0},
    {2267445,8,8,0},{2267957,9,8,0},{2268605,10,9,0},{2269505,11,9,0},
    {2270594,12,10,0},{2272034,13,10,0},{2273724,14,11,0},{2275880,15,11,0},
    {2278355,17,12,0},{2281823,18,12,0},{2285711,20,13,0},{2290911,22,13,0},
    {2297203,24,14,0},{2305267,27,15,0},{2316202,29,15,0},{2328817,32,16,0}
};

__constant__ int SP_OFF[10] = {0,4096,12096,27721,60489,124489,257140,519284,1050725,SP_TOTAL};
__constant__ int SPRES[9]   = {16,20,25,32,40,51,64,81,102};
__constant__ int TM_PRE[17] = {0,512,1160,2060,3149,4589,6279,8435,10910,14378,18266,23466,29758,37822,48757,61372,TM_TOTAL};
__constant__ int TR01[16]   = {8,9,10,11,12,13,14,15,17,18,20,22,24,27,29,32};
__constant__ int TR2[16]    = {8,8,9,9,10,10,11,11,12,12,13,13,14,15,15,16};

__device__ __forceinline__ void atomicMinF(float* a, float v) {
    if (v >= 0.0f) atomicMin((int*)a, __float_as_int(v));
    else           atomicMax((unsigned int*)a, __float_as_uint(v));
}
__device__ __forceinline__ void atomicMaxF(float* a, float v) {
    if (v >= 0.0f) atomicMax((int*)a, __float_as_int(v));
    else           atomicMin((unsigned int*)a, __float_as_uint(v));
}

__device__ __forceinline__ void ecef(float4 c, float& cx, float& cy, float& cz) {
    float latr = c.x * DEG2RAD;
    float lonr = c.y * DEG2RAD;
    float r    = EARTH_R + c.z;
    float sl, cl, so, co;
    sincosf(latr, &sl, &cl);
    sincosf(lonr, &so, &co);
    float rcl = r * cl;
    cx = rcl * co;
    cy = rcl * so;
    cz = r * sl;
}

__device__ __forceinline__ unsigned spread7(unsigned v) {
    v = (v | (v << 8)) & 0x0F00Fu;
    v = (v | (v << 4)) & 0xC30C3u;
    v = (v | (v << 2)) & 0x49249u;
    return v;
}

// pass 1: ECEF transform + min/max reduction; extra blocks zero g_hist
__global__ void __launch_bounds__(256) reduce_kernel(const float4* __restrict__ coords, int n) {
    if (blockIdx.x >= RED_BLOCKS) {
        int i = (blockIdx.x - RED_BLOCKS) * 256 + threadIdx.x;   // [0, 524288)
        ((int4*)g_hist)[i] = make_int4(0, 0, 0, 0);
        return;
    }
    float mn0 =  __int_as_float(0x7F800000), mn1 = mn0, mn2 = mn0, tmn = mn0;
    float mx0 = -mn0, mx1 = -mn0, mx2 = -mn0, tmx = -mn0;
    for (int i = blockIdx.x * blockDim.x + threadIdx.x; i < n; i += RED_BLOCKS * blockDim.x) {
        float4 c = __ldg(&coords[i]);
        float cx, cy, cz;
        ecef(c, cx, cy, cz);
        g_u[i] = make_float4(cx, cy, cz, c.w);
        mn0 = fminf(mn0, cx); mx0 = fmaxf(mx0, cx);
        mn1 = fminf(mn1, cy); mx1 = fmaxf(mx1, cy);
        mn2 = fminf(mn2, cz); mx2 = fmaxf(mx2, cz);
        tmn = fminf(tmn, c.w); tmx = fmaxf(tmx, c.w);
    }
    float v[8] = {mn0, mn1, mn2, mx0, mx1, mx2, tmn, tmx};
    #pragma unroll
    for (int o = 16; o > 0; o >>= 1) {
        #pragma unroll
        for (int q = 0; q < 8; q++) {
            float other = __shfl_xor_sync(0xFFFFFFFFu, v[q], o);
            bool is_min = (q < 3) || (q == 6);
            v[q] = is_min ? fminf(v[q], other) : fmaxf(v[q], other);
        }
    }
    __shared__ float s[8][8];
    int lane = threadIdx.x & 31, w = threadIdx.x >> 5;
    if (lane == 0) {
        #pragma unroll
        for (int q = 0; q < 8; q++) s[w][q] = v[q];
    }
    __syncthreads();
    if (threadIdx.x < 8) {
        int q = threadIdx.x;
        bool is_min = (q < 3) || (q == 6);
        float r = s[0][q];
        #pragma unroll
        for (int ww = 1; ww < 8; ww++)
            r = is_min ? fminf(r, s[ww][q]) : fmaxf(r, s[ww][q]);
        if (is_min) atomicMinF(&g_red[q], r);
        else        atomicMaxF(&g_red[q], r);
    }
}

// pass 2: rescale, 21-bit spatial morton key + histogram
__global__ void __launch_bounds__(256) normalize_kernel(int n) {
    int i = blockIdx.x * blockDim.x + threadIdx.x;
    if (i >= n) return;
    float4 c = g_u[i];
    float mnx = g_red[0], mny = g_red[1], mnz = g_red[2];
    float mxx = g_red[3], mxy = g_red[4], mxz = g_red[5];
    float tmn = g_red[6], tmx = g_red[7];
    float snx = (c.x - mnx) / (mxx - mnx);
    float sny = (c.y - mny) / (mxy - mny);
    float snz = (c.z - mnz) / (mxz - mnz);
    float tn  = (c.w - tmn) / (tmx - tmn);
    float ts  = (tn * 2.0f - 1.0f) * 0.9f;
    float ux = fminf(fmaxf((snx + 1.0f) * 0.5f, 0.0f), 1.0f);
    float uy = fminf(fmaxf((sny + 1.0f) * 0.5f, 0.0f), 1.0f);
    float uz = fminf(fmaxf((snz + 1.0f) * 0.5f, 0.0f), 1.0f);
    float ut = fminf(fmaxf((ts  + 1.0f) * 0.5f, 0.0f), 1.0f);
    g_u[i] = make_float4(ux, uy, uz, ut);

    unsigned bx = (unsigned)min(127, (int)(ux * 128.0f));
    unsigned by = (unsigned)min(127, (int)(uy * 128.0f));
    unsigned bz = (unsigned)min(127, (int)(uz * 128.0f));
    unsigned key = (spread7(bx) << 2) | (spread7(by) << 1) | spread7(bz);
    g_key[i] = (int)key;
    atomicAdd(&g_hist[key], 1);
}

__global__ void __launch_bounds__(256) scanA_kernel() {
    int t = threadIdx.x;
    int base4 = blockIdx.x * 256 + t;
    int4 h = ((const int4*)g_hist)[base4];
    int s = h.x + h.y + h.z + h.w;
    int incl = s;
    #pragma unroll
    for (int o = 1; o < 32; o <<= 1) {
        int v = __shfl_up_sync(0xFFFFFFFFu, incl, o);
        if ((t & 31) >= o) incl += v;
    }
    __shared__ int wsum[8];
    int lane = t & 31, w = t >> 5;
    if (lane == 31) wsum[w] = incl;
    __syncthreads();
    if (t < 8) {
        int v = wsum[t];
        #pragma unroll
        for (int o = 1; o < 8; o <<= 1) {
            int x = __shfl_up_sync(0xFFu, v, o);
            if (t >= o) v += x;
        }
        wsum[t] = v;
    }
    __syncthreads();
    int excl = incl - s + (w > 0 ? wsum[w - 1] : 0);
    int4 e;
    e.x = excl;
    e.y = excl + h.x;
    e.z = e.y + h.y;
    e.w = e.z + h.z;
    ((int4*)g_off)[base4] = e;
    if (t == 255) g_bsum[blockIdx.x] = excl + s;
}

// scatter with per-block re-derived 2048-chunk scan
__global__ void __launch_bounds__(256) scatter_kernel(int n) {
    int t = threadIdx.x;
    __shared__ int sboff[NCHUNK];
    {
        int4 a = ((const int4*)g_bsum)[t * 2];
        int4 b = ((const int4*)g_bsum)[t * 2 + 1];
        int c0 = a.x, c1 = a.y, c2 = a.z, c3 = a.w;
        int c4 = b.x, c5 = b.y, c6 = b.z, c7 = b.w;
        int s = c0 + c1 + c2 + c3 + c4 + c5 + c6 + c7;
        int incl = s;
        #pragma unroll
        for (int o = 1; o < 32; o <<= 1) {
            int v = __shfl_up_sync(0xFFFFFFFFu, incl, o);
            if ((t & 31) >= o) incl += v;
        }
        __shared__ int wsum[8];
        int lane = t & 31, w = t >> 5;
        if (lane == 31) wsum[w] = incl;
        __syncthreads();
        if (t < 8) {
            int v = wsum[t];
            #pragma unroll
            for (int o = 1; o < 8; o <<= 1) {
                int x = __shfl_up_sync(0xFFu, v, o);
                if (t >= o) v += x;
            }
            wsum[t] = v;
        }
        __syncthreads();
        int run = incl - s + (w > 0 ? wsum[w - 1] : 0);
        int base = t * 8;
        sboff[base + 0] = run; run += c0;
        sboff[base + 1] = run; run += c1;
        sboff[base + 2] = run; run += c2;
        sboff[base + 3] = run; run += c3;
        sboff[base + 4] = run; run += c4;
        sboff[base + 5] = run; run += c5;
        sboff[base + 6] = run; run += c6;
        sboff[base + 7] = run;
    }
    __syncthreads();

    int i = blockIdx.x * 256 + t;
    if (i >= n) return;
    int key = g_key[i];
    int pos = sboff[key >> 10] + atomicAdd(&g_off[key], 1);
    g_su[pos]   = g_u[i];
    g_sidx[pos] = i;
}

// Materialize dense grids: cell = 32B quad over the (y,z) corner square.
__global__ void __launch_bounds__(256) densify_kernel(
    const float* __restrict__ t_xyz, const float* __restrict__ t_xyt,
    const float* __restrict__ t_yzt, const float* __restrict__ t_xzt)
{
    int cell = blockIdx.x * 256 + threadIdx.x;
    if (cell >= DENSE_TOTAL) return;

    const float2* tab;
    int lvl, r01, r2, local;
    if (cell < SP_TOTAL) {
        lvl = 8;
        #pragma unroll
        for (int l = 8; l >= 1; l--) { if (cell < SP_OFF[l]) lvl = l - 1; }
        local = cell - SP_OFF[lvl];
        r01 = SPRES[lvl]; r2 = r01;
        tab = (const float2*)t_xyz;
    } else {
        int rem = cell - SP_TOTAL;
        int e = rem / TM_TOTAL;
        int lr = rem - e * TM_TOTAL;
        lvl = 15;
        #pragma unroll
        for (int l = 15; l >= 1; l--) { if (lr < TM_PRE[l]) lvl = l - 1; }
        local = lr - TM_PRE[lvl];
        r01 = TR01[lvl]; r2 = TR2[lvl];
        tab = (const float2*)((e == 0) ? t_xyt : (e == 1) ? t_yzt : t_xzt);
    }
    tab += (size_t)lvl * TBL_SIZE;

    int lz  = local % r2;
    int tmp = local / r2;
    int ly  = tmp % r01;
    int lx  = tmp / r01;
    int lz2 = min(lz + 1, r2  - 1);
    int ly2 = min(ly + 1, r01 - 1);

    unsigned hx  = (unsigned)lx;
    unsigned hy0 = (unsigned)ly  * 2654435761u;
    unsigned hy1 = (unsigned)ly2 * 2654435761u;
    unsigned hz0 = (unsigned)lz  * 805459861u;
    unsigned hz1 = (unsigned)lz2 * 805459861u;
    float2 a = __ldg(&tab[(hx ^ hy0 ^ hz0) & TBL_MASK]);   // (y,z)
    float2 b = __ldg(&tab[(hx ^ hy0 ^ hz1) & TBL_MASK]);   // (y,z+1)
    float2 c = __ldg(&tab[(hx ^ hy1 ^ hz0) & TBL_MASK]);   // (y+1,z)
    float2 d = __ldg(&tab[(hx ^ hy1 ^ hz1) & TBL_MASK]);   // (y+1,z+1)
    g_dense[cell * 2]     = make_float4(a.x, a.y, b.x, b.y);
    g_dense[cell * 2 + 1] = make_float4(c.x, c.y, d.x, d.y);
}

// block = 32 sorted points x 8 (enc,lvl) pairs; warp = one pair across 32 points
__global__ void __launch_bounds__(256) encode_kernel(
    const float* __restrict__ t_xyz, float2* __restrict__ out, int n)
{
    int lane = threadIdx.x & 31;
    int w    = threadIdx.x >> 5;
    int p    = blockIdx.x * 32 + lane;
    int pair = blockIdx.y * 8 + w;
    int enc  = pair >> 4;
    int lvl  = pair & 15;

    __shared__ float2 stage[32][9];
    float accx = 0.0f, accy = 0.0f;

    if (p < n) {
        float4 uv = g_su[p];
        float u0 = (enc == 2) ? uv.y : uv.x;
        float u1 = (enc <  2) ? uv.y : uv.z;
        float u2 = (enc == 0) ? uv.z : uv.w;

        int4 d = PAIR_DESC[pair];
        int r01 = d.y, r2 = d.z;

        float pos0 = u0 * ((float)r01 - 1.0f);
        float pos1 = u1 * ((float)r01 - 1.0f);
        float pos2 = u2 * ((float)r2  - 1.0f);
        int i0 = (int)pos0, i1 = (int)pos1, i2 = (int)pos2;
        float w0 = pos0 - (float)i0;
        float w1 = pos1 - (float)i1;
        float w2 = pos2 - (float)i2;
        int j0 = min(i0 + 1, r01 - 1);

        float2 f0, f1, f2, f3, f4, f5, f6, f7;
        if (d.x >= 0) {
            // quad-packed dense path: 2 cells (x0,x1), each 2 same-line float4s
            const float4* g = g_dense + (size_t)d.x * 2;
            int cA = ((i0 * r01 + i1) * r2 + i2) * 2;
            int cB = ((j0 * r01 + i1) * r2 + i2) * 2;
            float4 A0 = __ldg(&g[cA]);
            float4 A1 = __ldg(&g[cA + 1]);
            float4 B0 = __ldg(&g[cB]);
            float4 B1 = __ldg(&g[cB + 1]);
            f0 = make_float2(A0.x, A0.y); f4 = make_float2(A0.z, A0.w);
            f2 = make_float2(A1.x, A1.y); f6 = make_float2(A1.z, A1.w);
            f1 = make_float2(B0.x, B0.y); f5 = make_float2(B0.z, B0.w);
            f3 = make_float2(B1.x, B1.y); f7 = make_float2(B1.z, B1.w);
        } else {
            const float2* tab = (const float2*)t_xyz + (size_t)lvl * TBL_SIZE;
            int j1 = min(i1 + 1, r01 - 1);
            int j2 = min(i2 + 1, r2 - 1);
            unsigned hx0 = (unsigned)i0;
            unsigned hx1 = (unsigned)j0;
            unsigned hy0 = (unsigned)i1 * 2654435761u;
            unsigned hy1 = (unsigned)j1 * 2654435761u;
            unsigned hz0 = (unsigned)i2 * 805459861u;
            unsigned hz1 = (unsigned)j2 * 805459861u;
            f0 = __ldg(&tab[(hx0 ^ hy0 ^ hz0) & TBL_MASK]);
            f1 = __ldg(&tab[(hx1 ^ hy0 ^ hz0) & TBL_MASK]);
            f2 = __ldg(&tab[(hx0 ^ hy1 ^ hz0) & TBL_MASK]);
            f3 = __ldg(&tab[(hx1 ^ hy1 ^ hz0) & TBL_MASK]);
            f4 = __ldg(&tab[(hx0 ^ hy0 ^ hz1) & TBL_MASK]);
            f5 = __ldg(&tab[(hx1 ^ hy0 ^ hz1) & TBL_MASK]);
            f6 = __ldg(&tab[(hx0 ^ hy1 ^ hz1) & TBL_MASK]);
            f7 = __ldg(&tab[(hx1 ^ hy1 ^ hz1) & TBL_MASK]);
        }

        float a0 = 1.0f - w0, b0 = 1.0f - w1, c0w = 1.0f - w2;
        float w00 = a0 * b0, w10 = w0 * b0, w01 = a0 * w1, w11 = w0 * w1;

        accx = f0.x * (w00 * c0w);            accy = f0.y * (w00 * c0w);
        accx = fmaf(f1.x, w10 * c0w, accx);   accy = fmaf(f1.y, w10 * c0w, accy);
        accx = fmaf(f2.x, w01 * c0w, accx);   accy = fmaf(f2.y, w01 * c0w, accy);
        accx = fmaf(f3.x, w11 * c0w, accx);   accy = fmaf(f3.y, w11 * c0w, accy);
        accx = fmaf(f4.x, w00 * w2,  accx);   accy = fmaf(f4.y, w00 * w2,  accy);
        accx = fmaf(f5.x, w10 * w2,  accx);   accy = fmaf(f5.y, w10 * w2,  accy);
        accx = fmaf(f6.x, w01 * w2,  accx);   accy = fmaf(f6.y, w01 * w2,  accy);
        accx = fmaf(f7.x, w11 * w2,  accx);   accy = fmaf(f7.y, w11 * w2,  accy);
    }

    stage[lane][w] = make_float2(accx, accy);
    __syncthreads();

    int pl = threadIdx.x >> 3, q = threadIdx.x & 7;
    int pp = blockIdx.x * 32 + pl;
    if (pp < n) {
        int orig = g_sidx[pp];
        out[(size_t)orig * 64 + blockIdx.y * 8 + q] = stage[pl][q];
    }
}

extern "C" void kernel_launch(void* const* d_in, const int* in_sizes, int n_in,
                              void* d_out, int out_size)
{
    const float* coords = (const float*)d_in[0];
    const float* t_xyz  = (const float*)d_in[1];
    const float* t_xyt  = (const float*)d_in[2];
    const float* t_yzt  = (const float*)d_in[3];
    const float* t_xzt  = (const float*)d_in[4];
    int n = in_sizes[0] / 4;

    static cudaStream_t s2 = nullptr;
    static cudaEvent_t  evFork = nullptr, evDen = nullptr;
    if (s2 == nullptr) {
        cudaStreamCreateWithFlags(&s2, cudaStreamNonBlocking);
        cudaEventCreateWithFlags(&evFork, cudaEventDisableTiming);
        cudaEventCreateWithFlags(&evDen,  cudaEventDisableTiming);
    }

    // fork densify onto s2
    cudaEventRecord(evFork, 0);
    cudaStreamWaitEvent(s2, evFork, 0);
    densify_kernel<<<(DENSE_TOTAL + 255) / 256, 256, 0, s2>>>(t_xyz, t_xyt, t_yzt, t_xzt);
    cudaEventRecord(evDen, s2);

    // point pipeline on stream 0
    reduce_kernel<<<RED_BLOCKS + ZERO_BLOCKS, 256>>>((const float4*)coords, n);
    normalize_kernel<<<(n + 255) / 256, 256>>>(n);
    scanA_kernel<<<NCHUNK, 256>>>();
    scatter_kernel<<<(n + 255) / 256, 256>>>(n);

    // join, then encode
    cudaStreamWaitEvent(0, evDen, 0);
    dim3 grid((n + 31) / 32, 8);
    encode_kernel<<<grid, 256>>>(t_xyz, (float2*)d_out, n);
}

// round 17
// speedup vs baseline: 1.2413x; 1.2413x over previous
#include <cuda_runtime.h>

// ---------------------------------------------------------------------------
// Earth4D multires hash encode, sm_103a
// s2: densify   ||  s0: reduce(ecef+minmax+hist-zero) -> normalize(21-bit
// morton key + hist) -> scanA -> scatter(+chunk scan) ; join -> encode
// R15 structure; encode output stores use evict-first (__stcs) so the 256MB
// output stream does not evict the L2-resident hash/dense tables.
// ---------------------------------------------------------------------------

#define TBL_SIZE  (1 << 19)
#define TBL_MASK  0x7FFFFu
#define MAXN      500000
#define DEG2RAD   0.017453292519943295f
#define EARTH_R   6371000.0f

#define SP_TOTAL   2111933        // dense cells, spatial levels 0..8
#define TM_TOTAL   77756          // dense cells per temporal encoding
#define DENSE_TOTAL (SP_TOTAL + 3 * TM_TOTAL)   // 2345201

#define NBINS      2097152        // 21-bit spatial morton (x7,y7,z7)
#define NCHUNK     2048           // scanA blocks; 1024 bins per chunk
#define RED_BLOCKS 232
#define ZERO_BLOCKS 2048          // (NBINS/4)/256

// idempotent across graph replays: atomics re-derive the same min/max
__device__ float  g_red[8] = {3e38f, 3e38f, 3e38f, -3e38f, -3e38f, -3e38f, 3e38f, -3e38f};
__device__ float4 g_u[MAXN];
__device__ float4 g_su[MAXN];
__device__ int    g_sidx[MAXN];
__device__ int    g_key[MAXN];
__device__ int    g_hist[NBINS];
__device__ int    g_off[NBINS];
__device__ int    g_bsum[NCHUNK];
__device__ float4 g_dense[DENSE_TOTAL];

// per-(enc*16+lvl) descriptor: {dense_offset(-1 = hashed), r01, r2, 0}
__constant__ int4 PAIR_DESC[64] = {
    {0,16,16,0},{4096,20,20,0},{12096,25,25,0},{27721,32,32,0},
    {60489,40,40,0},{124489,51,51,0},{257140,64,64,0},{519284,81,81,0},
    {1050725,102,102,0},{-1,128,128,0},{-1,161,161,0},{-1,203,203,0},
    {-1,256,256,0},{-1,323,323,0},{-1,406,406,0},{-1,512,512,0},
    {2111933,8,8,0},{2112445,9,8,0},{2113093,10,9,0},{2113993,11,9,0},
    {2115082,12,10,0},{2116522,13,10,0},{2118212,14,11,0},{2120368,15,11,0},
    {2122843,17,12,0},{2126311,18,12,0},{2130199,20,13,0},{2135399,22,13,0},
    {2141691,24,14,0},{2149755,27,15,0},{2160690,29,15,0},{2173305,32,16,0},
    {2189689,8,8,0},{2190201,9,8,0},{2190849,10,9,0},{2191749,11,9,0},
    {2192838,12,10,0},{2194278,13,10,0},{2195968,14,11,0},{2198124,15,11,0},
    {2200599,17,12,0},{2204067,18,12,0},{2207955,20,13,0},{2213155,22,13,0},
    {2219447,24,14,0},{2227511,27,15,0},{2238446,29,15,0},{2251061,32,16,0},
    {2267445,8,8,0},{2267957,9,8,0},{2268605,10,9,0},{2269505,11,9,0},
    {2270594,12,10,0},{2272034,13,10,0},{2273724,14,11,0},{2275880,15,11,0},
    {2278355,17,12,0},{2281823,18,12,0},{2285711,20,13,0},{2290911,22,13,0},
    {2297203,24,14,0},{2305267,27,15,0},{2316202,29,15,0},{2328817,32,16,0}
};

__constant__ int SP_OFF[10] = {0,4096,12096,27721,60489,124489,257140,519284,1050725,SP_TOTAL};
__constant__ int SPRES[9]   = {16,20,25,32,40,51,64,81,102};
__constant__ int TM_PRE[17] = {0,512,1160,2060,3149,4589,6279,8435,10910,14378,18266,23466,29758,37822,48757,61372,TM_TOTAL};
__constant__ int TR01[16]   = {8,9,10,11,12,13,14,15,17,18,20,22,24,27,29,32};
__constant__ int TR2[16]    = {8,8,9,9,10,10,11,11,12,12,13,13,14,15,15,16};

__device__ __forceinline__ void atomicMinF(float* a, float v) {
    if (v >= 0.0f) atomicMin((int*)a, __float_as_int(v));
    else           atomicMax((unsigned int*)a, __float_as_uint(v));
}
__device__ __forceinline__ void atomicMaxF(float* a, float v) {
    if (v >= 0.0f) atomicMax((int*)a, __float_as_int(v));
    else           atomicMin((unsigned int*)a, __float_as_uint(v));
}

__device__ __forceinline__ void ecef(float4 c, float& cx, float& cy, float& cz) {
    float latr = c.x * DEG2RAD;
    float lonr = c.y * DEG2RAD;
    float r    = EARTH_R + c.z;
    float sl, cl, so, co;
    sincosf(latr, &sl, &cl);
    sincosf(lonr, &so, &co);
    float rcl = r * cl;
    cx = rcl * co;
    cy = rcl * so;
    cz = r * sl;
}

__device__ __forceinline__ unsigned spread7(unsigned v) {
    v = (v | (v << 8)) & 0x0F00Fu;
    v = (v | (v << 4)) & 0xC30C3u;
    v = (v | (v << 2)) & 0x49249u;
    return v;
}

// pass 1: ECEF transform + min/max reduction; extra blocks zero g_hist
__global__ void __launch_bounds__(256) reduce_kernel(const float4* __restrict__ coords, int n) {
    if (blockIdx.x >= RED_BLOCKS) {
        int i = (blockIdx.x - RED_BLOCKS) * 256 + threadIdx.x;   // [0, 524288)
        ((int4*)g_hist)[i] = make_int4(0, 0, 0, 0);
        return;
    }
    float mn0 =  __int_as_float(0x7F800000), mn1 = mn0, mn2 = mn0, tmn = mn0;
    float mx0 = -mn0, mx1 = -mn0, mx2 = -mn0, tmx = -mn0;
    for (int i = blockIdx.x * blockDim.x + threadIdx.x; i < n; i += RED_BLOCKS * blockDim.x) {
        float4 c = __ldg(&coords[i]);
        float cx, cy, cz;
        ecef(c, cx, cy, cz);
        g_u[i] = make_float4(cx, cy, cz, c.w);
        mn0 = fminf(mn0, cx); mx0 = fmaxf(mx0, cx);
        mn1 = fminf(mn1, cy); mx1 = fmaxf(mx1, cy);
        mn2 = fminf(mn2, cz); mx2 = fmaxf(mx2, cz);
        tmn = fminf(tmn, c.w); tmx = fmaxf(tmx, c.w);
    }
    float v[8] = {mn0, mn1, mn2, mx0, mx1, mx2, tmn, tmx};
    #pragma unroll
    for (int o = 16; o > 0; o >>= 1) {
        #pragma unroll
        for (int q = 0; q < 8; q++) {
            float other = __shfl_xor_sync(0xFFFFFFFFu, v[q], o);
            bool is_min = (q < 3) || (q == 6);
            v[q] = is_min ? fminf(v[q], other) : fmaxf(v[q], other);
        }
    }
    __shared__ float s[8][8];
    int lane = threadIdx.x & 31, w = threadIdx.x >> 5;
    if (lane == 0) {
        #pragma unroll
        for (int q = 0; q < 8; q++) s[w][q] = v[q];
    }
    __syncthreads();
    if (threadIdx.x < 8) {
        int q = threadIdx.x;
        bool is_min = (q < 3) || (q == 6);
        float r = s[0][q];
        #pragma unroll
        for (int ww = 1; ww < 8; ww++)
            r = is_min ? fminf(r, s[ww][q]) : fmaxf(r, s[ww][q]);
        if (is_min) atomicMinF(&g_red[q], r);
        else        atomicMaxF(&g_red[q], r);
    }
}

// pass 2: rescale, 21-bit spatial morton key + histogram
__global__ void __launch_bounds__(256) normalize_kernel(int n) {
    int i = blockIdx.x * blockDim.x + threadIdx.x;
    if (i >= n) return;
    float4 c = g_u[i];
    float mnx = g_red[0], mny = g_red[1], mnz = g_red[2];
    float mxx = g_red[3], mxy = g_red[4], mxz = g_red[5];
    float tmn = g_red[6], tmx = g_red[7];
    float snx = (c.x - mnx) / (mxx - mnx);
    float sny = (c.y - mny) / (mxy - mny);
    float snz = (c.z - mnz) / (mxz - mnz);
    float tn  = (c.w - tmn) / (tmx - tmn);
    float ts  = (tn * 2.0f - 1.0f) * 0.9f;
    float ux = fminf(fmaxf((snx + 1.0f) * 0.5f, 0.0f), 1.0f);
    float uy = fminf(fmaxf((sny + 1.0f) * 0.5f, 0.0f), 1.0f);
    float uz = fminf(fmaxf((snz + 1.0f) * 0.5f, 0.0f), 1.0f);
    float ut = fminf(fmaxf((ts  + 1.0f) * 0.5f, 0.0f), 1.0f);
    g_u[i] = make_float4(ux, uy, uz, ut);

    unsigned bx = (unsigned)min(127, (int)(ux * 128.0f));
    unsigned by = (unsigned)min(127, (int)(uy * 128.0f));
    unsigned bz = (unsigned)min(127, (int)(uz * 128.0f));
    unsigned key = (spread7(bx) << 2) | (spread7(by) << 1) | spread7(bz);
    g_key[i] = (int)key;
    atomicAdd(&g_hist[key], 1);
}

// scanA: 2048 blocks x 256 threads; block b scans bins [b*1024, (b+1)*1024)
__global__ void __launch_bounds__(256) scanA_kernel() {
    int t = threadIdx.x;
    int base4 = blockIdx.x * 256 + t;
    int4 h = ((const int4*)g_hist)[base4];
    int s = h.x + h.y + h.z + h.w;
    int incl = s;
    #pragma unroll
    for (int o = 1; o < 32; o <<= 1) {
        int v = __shfl_up_sync(0xFFFFFFFFu, incl, o);
        if ((t & 31) >= o) incl += v;
    }
    __shared__ int wsum[8];
    int lane = t & 31, w = t >> 5;
    if (lane == 31) wsum[w] = incl;
    __syncthreads();
    if (t < 8) {
        int v = wsum[t];
        #pragma unroll
        for (int o = 1; o < 8; o <<= 1) {
            int x = __shfl_up_sync(0xFFu, v, o);
            if (t >= o) v += x;
        }
        wsum[t] = v;
    }
    __syncthreads();
    int excl = incl - s + (w > 0 ? wsum[w - 1] : 0);
    int4 e;
    e.x = excl;
    e.y = excl + h.x;
    e.z = e.y + h.y;
    e.w = e.z + h.z;
    ((int4*)g_off)[base4] = e;
    if (t == 255) g_bsum[blockIdx.x] = excl + s;
}

// scatter with per-block re-derived 2048-chunk scan (no scanB kernel)
__global__ void __launch_bounds__(256) scatter_kernel(int n) {
    int t = threadIdx.x;
    __shared__ int sboff[NCHUNK];
    {
        // each thread owns 8 consecutive chunks
        int4 a = ((const int4*)g_bsum)[t * 2];
        int4 b = ((const int4*)g_bsum)[t * 2 + 1];
        int c0 = a.x, c1 = a.y, c2 = a.z, c3 = a.w;
        int c4 = b.x, c5 = b.y, c6 = b.z, c7 = b.w;
        int s = c0 + c1 + c2 + c3 + c4 + c5 + c6 + c7;
        int incl = s;
        #pragma unroll
        for (int o = 1; o < 32; o <<= 1) {
            int v = __shfl_up_sync(0xFFFFFFFFu, incl, o);
            if ((t & 31) >= o) incl += v;
        }
        __shared__ int wsum[8];
        int lane = t & 31, w = t >> 5;
        if (lane == 31) wsum[w] = incl;
        __syncthreads();
        if (t < 8) {
            int v = wsum[t];
            #pragma unroll
            for (int o = 1; o < 8; o <<= 1) {
                int x = __shfl_up_sync(0xFFu, v, o);
                if (t >= o) v += x;
            }
            wsum[t] = v;
        }
        __syncthreads();
        int run = incl - s + (w > 0 ? wsum[w - 1] : 0);
        int base = t * 8;
        sboff[base + 0] = run; run += c0;
        sboff[base + 1] = run; run += c1;
        sboff[base + 2] = run; run += c2;
        sboff[base + 3] = run; run += c3;
        sboff[base + 4] = run; run += c4;
        sboff[base + 5] = run; run += c5;
        sboff[base + 6] = run; run += c6;
        sboff[base + 7] = run;
    }
    __syncthreads();

    int i = blockIdx.x * 256 + t;
    if (i >= n) return;
    int key = g_key[i];
    int pos = sboff[key >> 10] + atomicAdd(&g_off[key], 1);
    g_su[pos]   = g_u[i];
    g_sidx[pos] = i;
}

__global__ void __launch_bounds__(256) densify_kernel(
    const float* __restrict__ t_xyz, const float* __restrict__ t_xyt,
    const float* __restrict__ t_yzt, const float* __restrict__ t_xzt)
{
    int cell = blockIdx.x * 256 + threadIdx.x;
    if (cell >= DENSE_TOTAL) return;

    const float2* tab;
    int lvl, r01, r2, local;
    if (cell < SP_TOTAL) {
        lvl = 8;
        #pragma unroll
        for (int l = 8; l >= 1; l--) { if (cell < SP_OFF[l]) lvl = l - 1; }
        local = cell - SP_OFF[lvl];
        r01 = SPRES[lvl]; r2 = r01;
        tab = (const float2*)t_xyz;
    } else {
        int rem = cell - SP_TOTAL;
        int e = rem / TM_TOTAL;
        int lr = rem - e * TM_TOTAL;
        lvl = 15;
        #pragma unroll
        for (int l = 15; l >= 1; l--) { if (lr < TM_PRE[l]) lvl = l - 1; }
        local = lr - TM_PRE[lvl];
        r01 = TR01[lvl]; r2 = TR2[lvl];
        tab = (const float2*)((e == 0) ? t_xyt : (e == 1) ? t_yzt : t_xzt);
    }
    tab += (size_t)lvl * TBL_SIZE;

    int lz  = local % r2;
    int tmp = local / r2;
    int ly  = tmp % r01;
    int lx  = tmp / r01;
    int lz2 = min(lz + 1, r2 - 1);

    unsigned hxy = (unsigned)lx ^ ((unsigned)ly * 2654435761u);
    unsigned i1 = (hxy ^ ((unsigned)lz  * 805459861u)) & TBL_MASK;
    unsigned i2 = (hxy ^ ((unsigned)lz2 * 805459861u)) & TBL_MASK;
    float2 a = __ldg(&tab[i1]);
    float2 b = __ldg(&tab[i2]);
    g_dense[cell] = make_float4(a.x, a.y, b.x, b.y);
}

// block = 32 sorted points x 8 (enc,lvl) pairs; warp = one pair across 32 points
__global__ void __launch_bounds__(256) encode_kernel(
    const float* __restrict__ t_xyz, float2* __restrict__ out, int n)
{
    int lane = threadIdx.x & 31;
    int w    = threadIdx.x >> 5;
    int p    = blockIdx.x * 32 + lane;
    int pair = blockIdx.y * 8 + w;
    int enc  = pair >> 4;
    int lvl  = pair & 15;

    __shared__ float2 stage[32][9];
    float accx = 0.0f, accy = 0.0f;

    if (p < n) {
        float4 uv = g_su[p];
        float u0 = (enc == 2) ? uv.y : uv.x;
        float u1 = (enc <  2) ? uv.y : uv.z;
        float u2 = (enc == 0) ? uv.z : uv.w;

        int4 d = PAIR_DESC[pair];
        int r01 = d.y, r2 = d.z;

        float pos0 = u0 * ((float)r01 - 1.0f);
        float pos1 = u1 * ((float)r01 - 1.0f);
        float pos2 = u2 * ((float)r2  - 1.0f);
        int i0 = (int)pos0, i1 = (int)pos1, i2 = (int)pos2;
        float w0 = pos0 - (float)i0;
        float w1 = pos1 - (float)i1;
        float w2 = pos2 - (float)i2;
        int j0 = min(i0 + 1, r01 - 1);
        int j1 = min(i1 + 1, r01 - 1);

        float2 f0, f1, f2, f3, f4, f5, f6, f7;
        if (d.x >= 0) {
            const float4* g = g_dense + d.x;
            float4 q00 = __ldg(&g[(i0 * r01 + i1) * r2 + i2]);
            float4 q10 = __ldg(&g[(j0 * r01 + i1) * r2 + i2]);
            float4 q01 = __ldg(&g[(i0 * r01 + j1) * r2 + i2]);
            float4 q11 = __ldg(&g[(j0 * r01 + j1) * r2 + i2]);
            f0 = make_float2(q00.x, q00.y); f4 = make_float2(q00.z, q00.w);
            f1 = make_float2(q10.x, q10.y); f5 = make_float2(q10.z, q10.w);
            f2 = make_float2(q01.x, q01.y); f6 = make_float2(q01.z, q01.w);
            f3 = make_float2(q11.x, q11.y); f7 = make_float2(q11.z, q11.w);
        } else {
            const float2* tab = (const float2*)t_xyz + (size_t)lvl * TBL_SIZE;
            int j2 = min(i2 + 1, r2 - 1);
            unsigned hx0 = (unsigned)i0;
            unsigned hx1 = (unsigned)j0;
            unsigned hy0 = (unsigned)i1 * 2654435761u;
            unsigned hy1 = (unsigned)j1 * 2654435761u;
            unsigned hz0 = (unsigned)i2 * 805459861u;
            unsigned hz1 = (unsigned)j2 * 805459861u;
            f0 = __ldg(&tab[(hx0 ^ hy0 ^ hz0) & TBL_MASK]);
            f1 = __ldg(&tab[(hx1 ^ hy0 ^ hz0) & TBL_MASK]);
            f2 = __ldg(&tab[(hx0 ^ hy1 ^ hz0) & TBL_MASK]);
            f3 = __ldg(&tab[(hx1 ^ hy1 ^ hz0) & TBL_MASK]);
            f4 = __ldg(&tab[(hx0 ^ hy0 ^ hz1) & TBL_MASK]);
            f5 = __ldg(&tab[(hx1 ^ hy0 ^ hz1) & TBL_MASK]);
            f6 = __ldg(&tab[(hx0 ^ hy1 ^ hz1) & TBL_MASK]);
            f7 = __ldg(&tab[(hx1 ^ hy1 ^ hz1) & TBL_MASK]);
        }

        float a0 = 1.0f - w0, b0 = 1.0f - w1, c0w = 1.0f - w2;
        float w00 = a0 * b0, w10 = w0 * b0, w01 = a0 * w1, w11 = w0 * w1;

        accx = f0.x * (w00 * c0w);            accy = f0.y * (w00 * c0w);
        accx = fmaf(f1.x, w10 * c0w, accx);   accy = fmaf(f1.y, w10 * c0w, accy);
        accx = fmaf(f2.x, w01 * c0w, accx);   accy = fmaf(f2.y, w01 * c0w, accy);
        accx = fmaf(f3.x, w11 * c0w, accx);   accy = fmaf(f3.y, w11 * c0w, accy);
        accx = fmaf(f4.x, w00 * w2,  accx);   accy = fmaf(f4.y, w00 * w2,  accy);
        accx = fmaf(f5.x, w10 * w2,  accx);   accy = fmaf(f5.y, w10 * w2,  accy);
        accx = fmaf(f6.x, w01 * w2,  accx);   accy = fmaf(f6.y, w01 * w2,  accy);
        accx = fmaf(f7.x, w11 * w2,  accx);   accy = fmaf(f7.y, w11 * w2,  accy);
    }

    stage[lane][w] = make_float2(accx, accy);
    __syncthreads();

    // writeback with evict-first stores: keep the table working set in L2
    int pl = threadIdx.x >> 3, q = threadIdx.x & 7;
    int pp = blockIdx.x * 32 + pl;
    if (pp < n) {
        int orig = g_sidx[pp];
        __stcs(&out[(size_t)orig * 64 + blockIdx.y * 8 + q], stage[pl][q]);
    }
}

extern "C" void kernel_launch(void* const* d_in, const int* in_sizes, int n_in,
                              void* d_out, int out_size)
{
    const float* coords = (const float*)d_in[0];
    const float* t_xyz  = (const float*)d_in[1];
    const float* t_xyt  = (const float*)d_in[2];
    const float* t_yzt  = (const float*)d_in[3];
    const float* t_xzt  = (const float*)d_in[4];
    int n = in_sizes[0] / 4;

    static cudaStream_t s2 = nullptr;
    static cudaEvent_t  evFork = nullptr, evDen = nullptr;
    if (s2 == nullptr) {
        cudaStreamCreateWithFlags(&s2, cudaStreamNonBlocking);
        cudaEventCreateWithFlags(&evFork, cudaEventDisableTiming);
        cudaEventCreateWithFlags(&evDen,  cudaEventDisableTiming);
    }

    // fork densify onto s2
    cudaEventRecord(evFork, 0);
    cudaStreamWaitEvent(s2, evFork, 0);
    densify_kernel<<<(DENSE_TOTAL + 255) / 256, 256, 0, s2>>>(t_xyz, t_xyt, t_yzt, t_xzt);
    cudaEventRecord(evDen, s2);

    // point pipeline on stream 0
    reduce_kernel<<<RED_BLOCKS + ZERO_BLOCKS, 256>>>((const float4*)coords, n);
    normalize_kernel<<<(n + 255) / 256, 256>>>(n);
    scanA_kernel<<<NCHUNK, 256>>>();
    scatter_kernel<<<(n + 255) / 256, 256>>>(n);

    // join, then encode
    cudaStreamWaitEvent(0, evDen, 0);
    dim3 grid((n + 31) / 32, 8);
    encode_kernel<<<grid, 256>>>(t_xyz, (float2*)d_out, n);
}